// round 13
// baseline (speedup 1.0000x reference)
#include <cuda_runtime.h>
#include <cstdint>
#include <math.h>

#define BATCH 4
#define CIN   256
#define CKEY  448
#define NPIX  4096

typedef unsigned long long u64;

__device__ __forceinline__ u64 pack2(float lo, float hi) {
    u64 r; asm("mov.b64 %0,{%1,%2};" : "=l"(r) : "f"(lo), "f"(hi)); return r;
}
__device__ __forceinline__ void unpack2(u64 v, float& lo, float& hi) {
    asm("mov.b64 {%0,%1},%2;" : "=f"(lo), "=f"(hi) : "l"(v));
}
__device__ __forceinline__ void fma2(u64& d, u64 a, u64 b) {
    asm("fma.rn.f32x2 %0,%1,%2,%0;" : "+l"(d) : "l"(a), "l"(b));
}
__device__ __forceinline__ u64 mul2(u64 a, u64 b) {
    u64 r; asm("mul.rn.f32x2 %0,%1,%2;" : "=l"(r) : "l"(a), "l"(b)); return r;
}
__device__ __forceinline__ uint32_t smem_u32(const void* p) {
    uint32_t a;
    asm("{ .reg .u64 t; cvta.to.shared.u64 t, %1; cvt.u32.u64 %0, t; }" : "=r"(a) : "l"(p));
    return a;
}
__device__ __forceinline__ void cpasync16(uint32_t dst, const void* src) {
    asm volatile("cp.async.cg.shared.global [%0], [%1], 16;" :: "r"(dst), "l"(src));
}
#define CP_COMMIT() asm volatile("cp.async.commit_group;")
#define CP_WAIT0()  asm volatile("cp.async.wait_group 0;")

__device__ float g_Fq[(size_t)BATCH * NPIX * CKEY];   // [b][n][ck]
__device__ float g_G [(size_t)BATCH * CKEY * NPIX];   // [b][ck][m]
__device__ float g_Hv[(size_t)BATCH * NPIX * CIN];    // [b][m][c]
__device__ float g_sM[BATCH * CIN];
__device__ float g_sR[BATCH * CIN];

// ---------------- projection: out = W @ X + b ----------------
__global__ __launch_bounds__(256) void proj_kernel(
    const float* __restrict__ X, const float* __restrict__ W,
    const float* __restrict__ bias, float* __restrict__ out,
    int inC, int outC, int transOut)
{
    __shared__ float Xs[128 * 20];
    __shared__ float Ws[64 * 20];
    const int n0 = blockIdx.x * 128, o0 = blockIdx.y * 64, b = blockIdx.z;
    const int tid = threadIdx.x, ty = tid >> 4, tx = tid & 15;
    const float* Xb = X + (size_t)b * inC * NPIX;

    float acc[8][4];
    #pragma unroll
    for (int i = 0; i < 8; i++)
        #pragma unroll
        for (int j = 0; j < 4; j++) acc[i][j] = 0.f;

    for (int c0 = 0; c0 < inC; c0 += 16) {
        __syncthreads();
        #pragma unroll
        for (int p = 0; p < 8; p++) {
            int idx = tid + p * 256;
            int nn = idx & 127, cc = idx >> 7;
            Xs[nn * 20 + cc] = Xb[(size_t)(c0 + cc) * NPIX + n0 + nn];
        }
        #pragma unroll
        for (int p = 0; p < 4; p++) {
            int idx = tid + p * 256;
            int cc = idx & 15, oo = idx >> 4;
            Ws[oo * 20 + cc] = W[(size_t)(o0 + oo) * inC + c0 + cc];
        }
        __syncthreads();
        #pragma unroll
        for (int cg = 0; cg < 4; cg++) {
            float4 bv[4];
            #pragma unroll
            for (int j = 0; j < 4; j++)
                bv[j] = *(const float4*)&Ws[(tx + 16 * j) * 20 + cg * 4];
            #pragma unroll
            for (int i = 0; i < 8; i++) {
                float4 av = *(const float4*)&Xs[(ty * 8 + i) * 20 + cg * 4];
                #pragma unroll
                for (int j = 0; j < 4; j++) {
                    acc[i][j] = fmaf(av.x, bv[j].x, acc[i][j]);
                    acc[i][j] = fmaf(av.y, bv[j].y, acc[i][j]);
                    acc[i][j] = fmaf(av.z, bv[j].z, acc[i][j]);
                    acc[i][j] = fmaf(av.w, bv[j].w, acc[i][j]);
                }
            }
        }
    }
    #pragma unroll
    for (int j = 0; j < 4; j++) {
        int o = o0 + tx + 16 * j;
        float bb = bias[o];
        #pragma unroll
        for (int i = 0; i < 8; i++) {
            int n = n0 + ty * 8 + i;
            float v = acc[i][j] + bb;
            if (transOut) out[((size_t)b * outC + o) * NPIX + n] = v;
            else          out[((size_t)b * NPIX + n) * outC + o] = v;
        }
    }
}

// ---------------- MVN stats per (b,c) ----------------
__global__ void mvn_stats_kernel(const float* __restrict__ x)
{
    const int bc = blockIdx.x;
    const float* p = x + (size_t)bc * NPIX;
    float s = 0.f, ss = 0.f;
    for (int i = threadIdx.x; i < NPIX; i += 256) {
        float v = p[i];
        s += v; ss = fmaf(v, v, ss);
    }
    #pragma unroll
    for (int o = 16; o > 0; o >>= 1) {
        s  += __shfl_xor_sync(0xffffffffu, s,  o);
        ss += __shfl_xor_sync(0xffffffffu, ss, o);
    }
    __shared__ float shs[8], shss[8];
    int w = threadIdx.x >> 5, l = threadIdx.x & 31;
    if (l == 0) { shs[w] = s; shss[w] = ss; }
    __syncthreads();
    if (threadIdx.x == 0) {
        float S = 0.f, SS = 0.f;
        #pragma unroll
        for (int i = 0; i < 8; i++) { S += shs[i]; SS += shss[i]; }
        float mean = S / (float)NPIX;
        float var  = (SS - S * mean) / (float)(NPIX - 1);
        g_sM[bc] = mean;
        g_sR[bc] = rsqrtf(var + 1e-5f);
    }
}

// ---------------- fused attention + epilogue (f32x2 + cp.async pipeline) -----
#define FQ_LD  452
#define BUF_LD 68
#define HV_LD  260
#define PS_LD  68
#define CHUNK_FLOATS 4352                       // max(64*68, 16*260)
#define ATTN_SMEM_BYTES ((32 * FQ_LD + 2 * CHUNK_FLOATS + 32 * PS_LD + 64) * 4)

__device__ __forceinline__ void load_G_chunk(uint32_t bufa, const float* Gb,
                                             int m0, int ch, int tid) {
    const int c0 = ch * 64;
    #pragma unroll
    for (int p = 0; p < 4; p++) {
        int idx4 = tid + p * 256;
        int mm4 = idx4 & 15, cc = idx4 >> 4;
        cpasync16(bufa + (uint32_t)(cc * BUF_LD + mm4 * 4) * 4u,
                  Gb + (size_t)(c0 + cc) * NPIX + m0 + mm4 * 4);
    }
}
__device__ __forceinline__ void load_H_chunk(uint32_t bufa, const float* Hb,
                                             int m0, int kc, int tid) {
    #pragma unroll
    for (int p = 0; p < 4; p++) {
        int idx4 = tid + p * 256;
        int c4 = idx4 & 63, kk = idx4 >> 6;
        cpasync16(bufa + (uint32_t)(kk * HV_LD + c4 * 4) * 4u,
                  Hb + (size_t)(m0 + kc * 16 + kk) * CIN + c4 * 4);
    }
}

__global__ __launch_bounds__(256, 2) void attn_kernel(
    const float* __restrict__ Fqg, const float* __restrict__ Gg,
    const float* __restrict__ Hvg,
    const float* __restrict__ content,
    const int*   __restrict__ cmask,
    const int*   __restrict__ smask,
    float* __restrict__ out)
{
    extern __shared__ float sm[];
    float* Fqs  = sm;                          // [32][452]
    float* bufA = Fqs + 32 * FQ_LD;            // chunk buffer 0
    float* bufB = bufA + CHUNK_FLOATS;         // chunk buffer 1
    float* Ps   = bufB + CHUNK_FLOATS;         // [32][68]
    float* smi  = Ps + 32 * PS_LD;             // [64]

    const int b = blockIdx.y, n0 = blockIdx.x * 32;
    const int tid = threadIdx.x, ty = tid >> 4, tx = tid & 15;
    const int r0 = 2 * ty, r1 = r0 + 1;

    const float* Fqb = Fqg + ((size_t)b * NPIX + n0) * CKEY;
    const float* Gb  = Gg  + (size_t)b * CKEY * NPIX;
    const float* Hb  = Hvg + (size_t)b * NPIX * CIN;

    float* bufp[2]  = {bufA, bufB};
    uint32_t bufu[2] = {smem_u32(bufA), smem_u32(bufB)};
    int par = 0;

    // stage Fq block [32 x 448] + first G chunk, one barrier
    #pragma unroll
    for (int p = 0; p < 14; p++) {
        int idx4 = tid + p * 256;
        int cc4 = idx4 % 112, nn = idx4 / 112;
        *(float4*)&Fqs[nn * FQ_LD + cc4 * 4] = *(const float4*)&Fqb[(size_t)nn * CKEY + cc4 * 4];
    }
    load_G_chunk(bufu[0], Gb, 0, 0, tid);
    CP_COMMIT(); CP_WAIT0();
    const bool rm0 = cmask[b * NPIX + n0 + r0] != 0;
    const bool rm1 = cmask[b * NPIX + n0 + r1] != 0;
    __syncthreads();

    u64 aM[2][8], aV[2][8];
    #pragma unroll
    for (int i = 0; i < 2; i++)
        #pragma unroll
        for (int c = 0; c < 8; c++) { aM[i][c] = 0ULL; aV[i][c] = 0ULL; }
    float accD0 = 0.f, accD1 = 0.f;

    for (int m0 = 0; m0 < NPIX; m0 += 64) {
        if (tid < 64) smi[tid] = (smask[b * NPIX + m0 + tid] == 0) ? 1.f : 0.f;

        u64 s0p0 = 0ULL, s0p1 = 0ULL, s1p0 = 0ULL, s1p1 = 0ULL;

        // ---- Phase A: S = Fq . G  (pipelined chunks) ----
        for (int ch = 0; ch < 7; ch++) {
            if (ch < 6) load_G_chunk(bufu[par ^ 1], Gb, m0, ch + 1, tid);
            else        load_H_chunk(bufu[par ^ 1], Hb, m0, 0, tid);
            CP_COMMIT();

            const float* buf = bufp[par];
            const int c0 = ch * 64;
            #pragma unroll 4
            for (int cs = 0; cs < 16; cs++) {
                int cc = cs * 4;
                float4 a0v = *(const float4*)&Fqs[r0 * FQ_LD + c0 + cc];
                float4 a1v = *(const float4*)&Fqs[r1 * FQ_LD + c0 + cc];
                const float* a0 = &a0v.x;
                const float* a1 = &a1v.x;
                #pragma unroll
                for (int q = 0; q < 4; q++) {
                    ulonglong2 bq = *(const ulonglong2*)&buf[(cc + q) * BUF_LD + tx * 4];
                    u64 a0d = pack2(a0[q], a0[q]);
                    u64 a1d = pack2(a1[q], a1[q]);
                    fma2(s0p0, a0d, bq.x); fma2(s0p1, a0d, bq.y);
                    fma2(s1p0, a1d, bq.x); fma2(s1p1, a1d, bq.y);
                }
            }
            CP_WAIT0(); __syncthreads(); par ^= 1;
        }

        // ---- Phase B: P = exp(S), masked -> 0 ----
        float s0[4], s1[4];
        unpack2(s0p0, s0[0], s0[1]); unpack2(s0p1, s0[2], s0[3]);
        unpack2(s1p0, s1[0], s1[1]); unpack2(s1p1, s1[2], s1[3]);
        #pragma unroll
        for (int j = 0; j < 4; j++) {
            float msk = smi[tx * 4 + j];
            float e0 = __expf(s0[j]); if (rm0 && msk > 0.5f) e0 = 0.f;
            float e1 = __expf(s1[j]); if (rm1 && msk > 0.5f) e1 = 0.f;
            Ps[r0 * PS_LD + tx * 4 + j] = e0;
            Ps[r1 * PS_LD + tx * 4 + j] = e1;
            accD0 += e0; accD1 += e1;
        }
        __syncwarp();   // Ps rows are produced & consumed within one warp

        // ---- Phase C: accumulate P.Hv, P.Hv^2 (pipelined chunks) ----
        for (int kc = 0; kc < 4; kc++) {
            if (kc < 3) load_H_chunk(bufu[par ^ 1], Hb, m0, kc + 1, tid);
            else        load_G_chunk(bufu[par ^ 1], Gb, (m0 + 64) & (NPIX - 1), 0, tid);
            CP_COMMIT();

            const float* buf = bufp[par];
            for (int kk = 0; kk < 16; kk++) {
                float w0 = Ps[r0 * PS_LD + kc * 16 + kk];
                float w1 = Ps[r1 * PS_LD + kc * 16 + kk];
                u64 w0p = pack2(w0, w0);
                u64 w1p = pack2(w1, w1);
                #pragma unroll
                for (int g = 0; g < 4; g++) {
                    ulonglong2 v = *(const ulonglong2*)&buf[kk * HV_LD + g * 64 + tx * 4];
                    u64 sx = mul2(v.x, v.x);
                    u64 sy = mul2(v.y, v.y);
                    fma2(aM[0][g*2],   w0p, v.x); fma2(aM[0][g*2+1], w0p, v.y);
                    fma2(aV[0][g*2],   w0p, sx ); fma2(aV[0][g*2+1], w0p, sy );
                    fma2(aM[1][g*2],   w1p, v.x); fma2(aM[1][g*2+1], w1p, v.y);
                    fma2(aV[1][g*2],   w1p, sx ); fma2(aV[1][g*2+1], w1p, sy );
                }
            }
            CP_WAIT0(); __syncthreads(); par ^= 1;
        }
    }

    // denominator: reduce across the 16 tx lanes sharing a row
    #pragma unroll
    for (int o = 1; o < 16; o <<= 1) {
        accD0 += __shfl_xor_sync(0xffffffffu, accD0, o);
        accD1 += __shfl_xor_sync(0xffffffffu, accD1, o);
    }
    float invD[2] = {1.f / accD0, 1.f / accD1};

    const float* Cb = content + (size_t)b * CIN * NPIX;
    float* Ob = out + (size_t)b * CIN * NPIX;
    #pragma unroll
    for (int i = 0; i < 2; i++) {
        int n = n0 + r0 + i;
        #pragma unroll
        for (int g = 0; g < 4; g++) {
            #pragma unroll
            for (int h = 0; h < 2; h++) {
                float m0v, m1v, v0v, v1v;
                unpack2(aM[i][g*2+h], m0v, m1v);
                unpack2(aV[i][g*2+h], v0v, v1v);
                #pragma unroll
                for (int e = 0; e < 2; e++) {
                    int c = g * 64 + tx * 4 + 2 * h + e;
                    float mean = (e ? m1v : m0v) * invD[i];
                    float m2   = (e ? v1v : v0v) * invD[i];
                    float sd = sqrtf(fmaxf(m2 - mean * mean, 0.f));
                    float x = Cb[(size_t)c * NPIX + n];
                    float nz = (x - g_sM[b * CIN + c]) * g_sR[b * CIN + c];
                    Ob[(size_t)c * NPIX + n] = fmaf(sd, nz, mean);
                }
            }
        }
    }
}

extern "C" void kernel_launch(void* const* d_in, const int* in_sizes, int n_in,
                              void* d_out, int out_size) {
    const float* content  = (const float*)d_in[0];
    const float* style    = (const float*)d_in[1];
    const float* ckey     = (const float*)d_in[2];
    const float* skey     = (const float*)d_in[3];
    const int*   cmask    = (const int*)d_in[4];
    const int*   smask    = (const int*)d_in[5];
    const float* Wf = (const float*)d_in[6];
    const float* bf = (const float*)d_in[7];
    const float* Wg = (const float*)d_in[8];
    const float* bg = (const float*)d_in[9];
    const float* Wh = (const float*)d_in[10];
    const float* bh = (const float*)d_in[11];
    float* out = (float*)d_out;

    float *Fq, *G, *Hv;
    cudaGetSymbolAddress((void**)&Fq, g_Fq);
    cudaGetSymbolAddress((void**)&G,  g_G);
    cudaGetSymbolAddress((void**)&Hv, g_Hv);
    cudaFuncSetAttribute(attn_kernel, cudaFuncAttributeMaxDynamicSharedMemorySize,
                         ATTN_SMEM_BYTES);

    proj_kernel<<<dim3(32, 7, BATCH), 256>>>(ckey, Wf, bf, Fq, CKEY, CKEY, 0);
    proj_kernel<<<dim3(32, 7, BATCH), 256>>>(skey, Wg, bg, G,  CKEY, CKEY, 1);
    proj_kernel<<<dim3(32, 4, BATCH), 256>>>(style, Wh, bh, Hv, CIN, CIN, 0);
    mvn_stats_kernel<<<BATCH * CIN, 256>>>(content);
    attn_kernel<<<dim3(NPIX / 32, BATCH), 256, ATTN_SMEM_BYTES>>>(
        Fq, G, Hv, content, cmask, smask, out);
}

// round 14
// speedup vs baseline: 1.0143x; 1.0143x over previous
#include <cuda_runtime.h>
#include <cstdint>
#include <math.h>

#define BATCH 4
#define CIN   256
#define CKEY  448
#define NPIX  4096

typedef unsigned long long u64;

__device__ __forceinline__ u64 pack2(float lo, float hi) {
    u64 r; asm("mov.b64 %0,{%1,%2};" : "=l"(r) : "f"(lo), "f"(hi)); return r;
}
__device__ __forceinline__ void unpack2(u64 v, float& lo, float& hi) {
    asm("mov.b64 {%0,%1},%2;" : "=f"(lo), "=f"(hi) : "l"(v));
}
__device__ __forceinline__ void fma2(u64& d, u64 a, u64 b) {
    asm("fma.rn.f32x2 %0,%1,%2,%0;" : "+l"(d) : "l"(a), "l"(b));
}
__device__ __forceinline__ u64 mul2(u64 a, u64 b) {
    u64 r; asm("mul.rn.f32x2 %0,%1,%2;" : "=l"(r) : "l"(a), "l"(b)); return r;
}
__device__ __forceinline__ uint32_t smem_u32(const void* p) {
    uint32_t a;
    asm("{ .reg .u64 t; cvta.to.shared.u64 t, %1; cvt.u32.u64 %0, t; }" : "=r"(a) : "l"(p));
    return a;
}
__device__ __forceinline__ void cpasync16(uint32_t dst, const void* src) {
    asm volatile("cp.async.cg.shared.global [%0], [%1], 16;" :: "r"(dst), "l"(src));
}
#define CP_COMMIT() asm volatile("cp.async.commit_group;")
#define CP_WAIT0()  asm volatile("cp.async.wait_group 0;")

__device__ float g_Fq[(size_t)BATCH * NPIX * CKEY];   // [b][n][ck]
__device__ float g_G [(size_t)BATCH * NPIX * CKEY];   // [b][m][ck] token-major
__device__ float g_Hv[(size_t)BATCH * NPIX * CIN];    // [b][m][c]
__device__ float g_sM[BATCH * CIN];
__device__ float g_sR[BATCH * CIN];

// ---------------- projection: out[b][n][o] = sum_c W[o][c] X[b][c][n] + b[o] ----
__global__ __launch_bounds__(256) void proj_kernel(
    const float* __restrict__ X, const float* __restrict__ W,
    const float* __restrict__ bias, float* __restrict__ out, int inC, int outC)
{
    __shared__ float Xs[128 * 20];
    __shared__ float Ws[64 * 20];
    const int n0 = blockIdx.x * 128, o0 = blockIdx.y * 64, b = blockIdx.z;
    const int tid = threadIdx.x, ty = tid >> 4, tx = tid & 15;
    const float* Xb = X + (size_t)b * inC * NPIX;

    float acc[8][4];
    #pragma unroll
    for (int i = 0; i < 8; i++)
        #pragma unroll
        for (int j = 0; j < 4; j++) acc[i][j] = 0.f;

    for (int c0 = 0; c0 < inC; c0 += 16) {
        __syncthreads();
        #pragma unroll
        for (int p = 0; p < 8; p++) {
            int idx = tid + p * 256, nn = idx & 127, cc = idx >> 7;
            Xs[nn * 20 + cc] = Xb[(size_t)(c0 + cc) * NPIX + n0 + nn];
        }
        #pragma unroll
        for (int p = 0; p < 4; p++) {
            int idx = tid + p * 256, cc = idx & 15, oo = idx >> 4;
            Ws[oo * 20 + cc] = W[(size_t)(o0 + oo) * inC + c0 + cc];
        }
        __syncthreads();
        #pragma unroll
        for (int cg = 0; cg < 4; cg++) {
            float4 bv[4];
            #pragma unroll
            for (int j = 0; j < 4; j++)
                bv[j] = *(const float4*)&Ws[(tx + 16 * j) * 20 + cg * 4];
            #pragma unroll
            for (int i = 0; i < 8; i++) {
                float4 av = *(const float4*)&Xs[(ty * 8 + i) * 20 + cg * 4];
                #pragma unroll
                for (int j = 0; j < 4; j++) {
                    acc[i][j] = fmaf(av.x, bv[j].x, acc[i][j]);
                    acc[i][j] = fmaf(av.y, bv[j].y, acc[i][j]);
                    acc[i][j] = fmaf(av.z, bv[j].z, acc[i][j]);
                    acc[i][j] = fmaf(av.w, bv[j].w, acc[i][j]);
                }
            }
        }
    }
    #pragma unroll
    for (int j = 0; j < 4; j++) {
        int o = o0 + tx + 16 * j;
        float bb = bias[o];
        #pragma unroll
        for (int i = 0; i < 8; i++)
            out[((size_t)b * NPIX + n0 + ty * 8 + i) * outC + o] = acc[i][j] + bb;
    }
}

// ---------------- MVN stats per (b,c) ----------------
__global__ void mvn_stats_kernel(const float* __restrict__ x)
{
    const int bc = blockIdx.x;
    const float* p = x + (size_t)bc * NPIX;
    float s = 0.f, ss = 0.f;
    for (int i = threadIdx.x; i < NPIX; i += 256) {
        float v = p[i]; s += v; ss = fmaf(v, v, ss);
    }
    #pragma unroll
    for (int o = 16; o > 0; o >>= 1) {
        s  += __shfl_xor_sync(0xffffffffu, s,  o);
        ss += __shfl_xor_sync(0xffffffffu, ss, o);
    }
    __shared__ float shs[8], shss[8];
    int w = threadIdx.x >> 5, l = threadIdx.x & 31;
    if (l == 0) { shs[w] = s; shss[w] = ss; }
    __syncthreads();
    if (threadIdx.x == 0) {
        float S = 0.f, SS = 0.f;
        #pragma unroll
        for (int i = 0; i < 8; i++) { S += shs[i]; SS += shss[i]; }
        float mean = S / (float)NPIX;
        float var  = (SS - S * mean) / (float)(NPIX - 1);
        g_sM[bc] = mean; g_sR[bc] = rsqrtf(var + 1e-5f);
    }
}

// ---------------- fused attention + epilogue ----------------
#define FQ_LD  452
#define GB_LD  68
#define HV_LD  260
#define PS_LD  68
#define CHUNK_FLOATS 4416
#define ATTN_SMEM_FLOATS (32 * FQ_LD + 64 + 2 * CHUNK_FLOATS + 32 * PS_LD + 64 + 32)
#define ATTN_SMEM_BYTES  (ATTN_SMEM_FLOATS * 4)

__device__ __forceinline__ void load_G_chunk(uint32_t bufa, const float* Gb,
                                             int m0, int ch, int tid) {
    const int c0 = ch * 64;
    #pragma unroll
    for (int p = 0; p < 4; p++) {
        int idx = tid + p * 256;
        int key = idx >> 4, c16 = idx & 15;
        cpasync16(bufa + (uint32_t)(key * GB_LD + ((key >> 2) << 2) + c16 * 4) * 4u,
                  Gb + (size_t)(m0 + key) * CKEY + c0 + c16 * 4);
    }
}
__device__ __forceinline__ void load_H_chunk(uint32_t bufa, const float* Hb,
                                             int m0, int kc, int tid) {
    #pragma unroll
    for (int p = 0; p < 4; p++) {
        int idx = tid + p * 256;
        int c4 = idx & 63, kk = idx >> 6;
        cpasync16(bufa + (uint32_t)(kk * HV_LD + c4 * 4) * 4u,
                  Hb + (size_t)(m0 + kc * 16 + kk) * CIN + c4 * 4);
    }
}

__global__ __launch_bounds__(256, 2) void attn_kernel(
    const float* __restrict__ Fqg, const float* __restrict__ Gg,
    const float* __restrict__ Hvg,
    const float* __restrict__ content,
    const int*   __restrict__ cmask,
    const int*   __restrict__ smask,
    float* __restrict__ out)
{
    extern __shared__ float sm[];
    float* Fqs  = sm;                              // 32*452 + 64 skew pad
    float* bufA = Fqs + 32 * FQ_LD + 64;
    float* bufB = bufA + CHUNK_FLOATS;
    float* Ps   = bufB + CHUNK_FLOATS;             // [32][68]
    float* smi  = Ps + 32 * PS_LD;                 // [64]
    float* rowD = smi + 64;                        // [32]

    const int b = blockIdx.y, n0 = blockIdx.x * 32;
    const int tid = threadIdx.x;
    const int ty = tid >> 4, tx = tid & 15;        // phase C / epilogue
    const int r0 = 2 * ty, r1 = r0 + 1;
    const int w = tid >> 5, wr = w >> 2, wk = w & 3;  // phase A: 16r x 16k per warp
    const int rg = (tid & 31) >> 2, kx = tid & 3;
    const int rbase = wr * 16 + rg * 2;
    const int kb = wk * 16 + kx * 4;
    const int aoff0 = rbase * FQ_LD + ((rbase >> 1) << 2);
    const int aoff1 = aoff0 + FQ_LD + 4;           // row rbase+1 skew: ((rbase+1)>>1)<<2 = same + 4? no:
    // careful: skew(r)=4*(r>>1); skew(rbase)=4*(rbase>>1), skew(rbase+1)= same (rbase even) -> +0
    const int aoff1c = aoff0 + FQ_LD;

    const float* Fqb = Fqg + ((size_t)b * NPIX + n0) * CKEY;
    const float* Gb  = Gg  + (size_t)b * NPIX * CKEY;
    const float* Hb  = Hvg + (size_t)b * NPIX * CIN;

    float* bufp[2]  = {bufA, bufB};
    uint32_t bufu[2] = {smem_u32(bufA), smem_u32(bufB)};
    int par = 0;

    #pragma unroll
    for (int p = 0; p < 14; p++) {
        int idx4 = tid + p * 256;
        int cc4 = idx4 % 112, nn = idx4 / 112;
        *(float4*)&Fqs[nn * FQ_LD + ((nn >> 1) << 2) + cc4 * 4] =
            *(const float4*)&Fqb[(size_t)nn * CKEY + cc4 * 4];
    }
    if (tid < 32) rowD[tid] = 0.f;
    load_G_chunk(bufu[0], Gb, 0, 0, tid);
    CP_COMMIT(); CP_WAIT0();
    const bool rmA0 = cmask[b * NPIX + n0 + rbase] != 0;
    const bool rmA1 = cmask[b * NPIX + n0 + rbase + 1] != 0;
    __syncthreads();

    u64 aM[2][8], aV[2][8];
    #pragma unroll
    for (int i = 0; i < 2; i++)
        #pragma unroll
        for (int c = 0; c < 8; c++) { aM[i][c] = 0ULL; aV[i][c] = 0ULL; }
    float accD[2] = {0.f, 0.f};

    for (int m0 = 0; m0 < NPIX; m0 += 64) {
        if (tid < 64) smi[tid] = (smask[b * NPIX + m0 + tid] == 0) ? 1.f : 0.f;

        u64 s2[2][4] = {{0ULL,0ULL,0ULL,0ULL},{0ULL,0ULL,0ULL,0ULL}};

        // Phase A: channel-pair f32x2, no broadcast MOVs
        for (int ch = 0; ch < 7; ch++) {
            if (ch < 6) load_G_chunk(bufu[par ^ 1], Gb, m0, ch + 1, tid);
            else        load_H_chunk(bufu[par ^ 1], Hb, m0, 0, tid);
            CP_COMMIT();

            const float* buf = bufp[par];
            const int a0 = aoff0 + ch * 64, a1 = aoff1c + ch * 64;
            const int bo = kb * GB_LD + ((kb >> 2) << 2);
            #pragma unroll
            for (int c4 = 0; c4 < 16; c4++) {
                ulonglong2 A0 = *(const ulonglong2*)&Fqs[a0 + c4 * 4];
                ulonglong2 A1 = *(const ulonglong2*)&Fqs[a1 + c4 * 4];
                #pragma unroll
                for (int j = 0; j < 4; j++) {
                    ulonglong2 B = *(const ulonglong2*)&buf[bo + j * GB_LD + c4 * 4];
                    fma2(s2[0][j], A0.x, B.x); fma2(s2[0][j], A0.y, B.y);
                    fma2(s2[1][j], A1.x, B.x); fma2(s2[1][j], A1.y, B.y);
                }
            }
            CP_WAIT0(); __syncthreads(); par ^= 1;
        }

        // Phase B: horizontal add + exp + mask
        #pragma unroll
        for (int i = 0; i < 2; i++) {
            bool rm = i ? rmA1 : rmA0;
            float e[4];
            #pragma unroll
            for (int j = 0; j < 4; j++) {
                float lo, hi; unpack2(s2[i][j], lo, hi);
                float ee = __expf(lo + hi);
                if (rm && smi[kb + j] > 0.5f) ee = 0.f;
                e[j] = ee; accD[i] += ee;
            }
            *(float4*)&Ps[(rbase + i) * PS_LD + kb] = make_float4(e[0], e[1], e[2], e[3]);
        }
        __syncthreads();

        // Phase C: accumulate P.Hv, P.Hv^2
        for (int kc = 0; kc < 4; kc++) {
            if (kc < 3) load_H_chunk(bufu[par ^ 1], Hb, m0, kc + 1, tid);
            else        load_G_chunk(bufu[par ^ 1], Gb, (m0 + 64) & (NPIX - 1), 0, tid);
            CP_COMMIT();

            const float* buf = bufp[par];
            #pragma unroll 4
            for (int kk = 0; kk < 16; kk++) {
                float w0 = Ps[r0 * PS_LD + kc * 16 + kk];
                float w1 = Ps[r1 * PS_LD + kc * 16 + kk];
                u64 w0p = pack2(w0, w0);
                u64 w1p = pack2(w1, w1);
                #pragma unroll
                for (int g = 0; g < 4; g++) {
                    ulonglong2 v = *(const ulonglong2*)&buf[kk * HV_LD + g * 64 + tx * 4];
                    u64 sx = mul2(v.x, v.x);
                    u64 sy = mul2(v.y, v.y);
                    fma2(aM[0][g*2],   w0p, v.x); fma2(aM[0][g*2+1], w0p, v.y);
                    fma2(aV[0][g*2],   w0p, sx ); fma2(aV[0][g*2+1], w0p, sy );
                    fma2(aM[1][g*2],   w1p, v.x); fma2(aM[1][g*2+1], w1p, v.y);
                    fma2(aV[1][g*2],   w1p, sx ); fma2(aV[1][g*2+1], w1p, sy );
                }
            }
            CP_WAIT0(); __syncthreads(); par ^= 1;
        }
    }

    // denominators: sum over kx lanes, then across wk warps via smem atomics
    #pragma unroll
    for (int o = 1; o < 4; o <<= 1) {
        accD[0] += __shfl_xor_sync(0xffffffffu, accD[0], o);
        accD[1] += __shfl_xor_sync(0xffffffffu, accD[1], o);
    }
    if (kx == 0) {
        atomicAdd(&rowD[rbase],     accD[0]);
        atomicAdd(&rowD[rbase + 1], accD[1]);
    }
    __syncthreads();
    float invD[2] = {1.f / rowD[r0], 1.f / rowD[r1]};

    const float* Cb = content + (size_t)b * CIN * NPIX;
    float* Ob = out + (size_t)b * CIN * NPIX;
    #pragma unroll
    for (int i = 0; i < 2; i++) {
        int n = n0 + r0 + i;
        #pragma unroll
        for (int g = 0; g < 4; g++) {
            #pragma unroll
            for (int h = 0; h < 2; h++) {
                float m0v, m1v, v0v, v1v;
                unpack2(aM[i][g*2+h], m0v, m1v);
                unpack2(aV[i][g*2+h], v0v, v1v);
                #pragma unroll
                for (int e = 0; e < 2; e++) {
                    int c = g * 64 + tx * 4 + 2 * h + e;
                    float mean = (e ? m1v : m0v) * invD[i];
                    float m2   = (e ? v1v : v0v) * invD[i];
                    float sd = sqrtf(fmaxf(m2 - mean * mean, 0.f));
                    float x = Cb[(size_t)c * NPIX + n];
                    float nz = (x - g_sM[b * CIN + c]) * g_sR[b * CIN + c];
                    Ob[(size_t)c * NPIX + n] = fmaf(sd, nz, mean);
                }
            }
        }
    }
}

extern "C" void kernel_launch(void* const* d_in, const int* in_sizes, int n_in,
                              void* d_out, int out_size) {
    const float* content = (const float*)d_in[0];
    const float* style   = (const float*)d_in[1];
    const float* ckey    = (const float*)d_in[2];
    const float* skey    = (const float*)d_in[3];
    const int*   cmask   = (const int*)d_in[4];
    const int*   smask   = (const int*)d_in[5];
    const float* Wf = (const float*)d_in[6];
    const float* bf = (const float*)d_in[7];
    const float* Wg = (const float*)d_in[8];
    const float* bg = (const float*)d_in[9];
    const float* Wh = (const float*)d_in[10];
    const float* bh = (const float*)d_in[11];
    float* out = (float*)d_out;

    float *Fq, *G, *Hv;
    cudaGetSymbolAddress((void**)&Fq, g_Fq);
    cudaGetSymbolAddress((void**)&G,  g_G);
    cudaGetSymbolAddress((void**)&Hv, g_Hv);
    cudaFuncSetAttribute(attn_kernel, cudaFuncAttributeMaxDynamicSharedMemorySize,
                         ATTN_SMEM_BYTES);

    proj_kernel<<<dim3(32, 7, BATCH), 256>>>(ckey,  Wf, bf, Fq, CKEY, CKEY);
    proj_kernel<<<dim3(32, 7, BATCH), 256>>>(skey,  Wg, bg, G,  CKEY, CKEY);
    proj_kernel<<<dim3(32, 4, BATCH), 256>>>(style, Wh, bh, Hv, CIN, CIN);
    mvn_stats_kernel<<<BATCH * CIN, 256>>>(content);
    attn_kernel<<<dim3(NPIX / 32, BATCH), 256, ATTN_SMEM_BYTES>>>(
        Fq, G, Hv, content, cmask, smask, out);
}

// round 15
// speedup vs baseline: 1.6162x; 1.5934x over previous
#include <cuda_runtime.h>
#include <cstdint>
#include <math.h>

#define BATCH 4
#define CIN   256
#define CKEY  448
#define NPIX  4096

typedef unsigned long long u64;

__device__ __forceinline__ u64 pack2(float lo, float hi) {
    u64 r; asm("mov.b64 %0,{%1,%2};" : "=l"(r) : "f"(lo), "f"(hi)); return r;
}
__device__ __forceinline__ void unpack2(u64 v, float& lo, float& hi) {
    asm("mov.b64 {%0,%1},%2;" : "=f"(lo), "=f"(hi) : "l"(v));
}
__device__ __forceinline__ void fma2(u64& d, u64 a, u64 b) {
    asm("fma.rn.f32x2 %0,%1,%2,%0;" : "+l"(d) : "l"(a), "l"(b));
}
__device__ __forceinline__ uint32_t smem_u32(const void* p) {
    uint32_t a;
    asm("{ .reg .u64 t; cvta.to.shared.u64 t, %1; cvt.u32.u64 %0, t; }" : "=r"(a) : "l"(p));
    return a;
}
__device__ __forceinline__ void cpasync16(uint32_t dst, const void* src) {
    asm volatile("cp.async.cg.shared.global [%0], [%1], 16;" :: "r"(dst), "l"(src));
}
#define CP_COMMIT() asm volatile("cp.async.commit_group;")
#define CP_WAIT0()  asm volatile("cp.async.wait_group 0;")

// scratch (__device__ globals: the sanctioned no-alloc path)
__device__ float g_Fq[(size_t)BATCH * CKEY * NPIX];      // [b][ck][n] k-major
__device__ float g_G [(size_t)BATCH * CKEY * NPIX];      // [b][ck][m] k-major
__device__ float g_HX[(size_t)BATCH * NPIX * 2 * CIN];   // [b][m][2c] interleave (v, v^2)
__device__ float g_P [(size_t)BATCH * NPIX * NPIX];      // [b][m][n]  = P^T
__device__ float g_D [(size_t)BATCH * NPIX];             // softmax denominators
__device__ float g_sM[BATCH * CIN];
__device__ float g_sR[BATCH * CIN];

// ---------------- projection ----------------
// mode 0: out[(b*outC+o)*NPIX+n] = v          (k-major)
// mode 1: out[(b*NPIX+n)*2*outC + 2o] = v, +1 = v*v  (interleaved HX)
__global__ __launch_bounds__(256) void proj_kernel(
    const float* __restrict__ X, const float* __restrict__ W,
    const float* __restrict__ bias, float* __restrict__ out,
    int inC, int outC, int mode)
{
    __shared__ float Xs[128 * 20];
    __shared__ float Ws[64 * 20];
    const int n0 = blockIdx.x * 128, o0 = blockIdx.y * 64, b = blockIdx.z;
    const int tid = threadIdx.x, ty = tid >> 4, tx = tid & 15;
    const float* Xb = X + (size_t)b * inC * NPIX;

    float acc[8][4];
    #pragma unroll
    for (int i = 0; i < 8; i++)
        #pragma unroll
        for (int j = 0; j < 4; j++) acc[i][j] = 0.f;

    for (int c0 = 0; c0 < inC; c0 += 16) {
        __syncthreads();
        #pragma unroll
        for (int p = 0; p < 8; p++) {
            int idx = tid + p * 256, nn = idx & 127, cc = idx >> 7;
            Xs[nn * 20 + cc] = Xb[(size_t)(c0 + cc) * NPIX + n0 + nn];
        }
        #pragma unroll
        for (int p = 0; p < 4; p++) {
            int idx = tid + p * 256, cc = idx & 15, oo = idx >> 4;
            Ws[oo * 20 + cc] = W[(size_t)(o0 + oo) * inC + c0 + cc];
        }
        __syncthreads();
        #pragma unroll
        for (int cg = 0; cg < 4; cg++) {
            float4 bv[4];
            #pragma unroll
            for (int j = 0; j < 4; j++)
                bv[j] = *(const float4*)&Ws[(tx + 16 * j) * 20 + cg * 4];
            #pragma unroll
            for (int i = 0; i < 8; i++) {
                float4 av = *(const float4*)&Xs[(ty * 8 + i) * 20 + cg * 4];
                #pragma unroll
                for (int j = 0; j < 4; j++) {
                    acc[i][j] = fmaf(av.x, bv[j].x, acc[i][j]);
                    acc[i][j] = fmaf(av.y, bv[j].y, acc[i][j]);
                    acc[i][j] = fmaf(av.z, bv[j].z, acc[i][j]);
                    acc[i][j] = fmaf(av.w, bv[j].w, acc[i][j]);
                }
            }
        }
    }
    #pragma unroll
    for (int j = 0; j < 4; j++) {
        int o = o0 + tx + 16 * j;
        float bb = bias[o];
        #pragma unroll
        for (int i = 0; i < 8; i++) {
            int n = n0 + ty * 8 + i;
            float v = acc[i][j] + bb;
            if (mode == 0) out[((size_t)b * outC + o) * NPIX + n] = v;
            else {
                size_t base = ((size_t)b * NPIX + n) * (2 * outC) + 2 * o;
                out[base] = v; out[base + 1] = v * v;
            }
        }
    }
}

// ---------------- MVN stats per (b,c) ----------------
__global__ void mvn_stats_kernel(const float* __restrict__ x)
{
    const int bc = blockIdx.x;
    const float* p = x + (size_t)bc * NPIX;
    float s = 0.f, ss = 0.f;
    for (int i = threadIdx.x; i < NPIX; i += 256) {
        float v = p[i]; s += v; ss = fmaf(v, v, ss);
    }
    #pragma unroll
    for (int o = 16; o > 0; o >>= 1) {
        s  += __shfl_xor_sync(0xffffffffu, s,  o);
        ss += __shfl_xor_sync(0xffffffffu, ss, o);
    }
    __shared__ float shs[8], shss[8];
    int w = threadIdx.x >> 5, l = threadIdx.x & 31;
    if (l == 0) { shs[w] = s; shss[w] = ss; }
    __syncthreads();
    if (threadIdx.x == 0) {
        float S = 0.f, SS = 0.f;
        #pragma unroll
        for (int i = 0; i < 8; i++) { S += shs[i]; SS += shss[i]; }
        float mean = S / (float)NPIX;
        float var  = (SS - S * mean) / (float)(NPIX - 1);
        g_sM[bc] = mean; g_sR[bc] = rsqrtf(var + 1e-5f);
    }
}

__global__ void zero_kernel(float* p, int n) {
    int i = blockIdx.x * blockDim.x + threadIdx.x;
    if (i < n) p[i] = 0.f;
}

// ---------------- shared GEMM pieces: 128x128 tile, 8x8 micro ----------------
#define TLD 132
__device__ __forceinline__ void load_tile(uint32_t sa, const float* src,
                                          size_t row_stride, int tid) {
    // 16 rows x 128 cols; src points at row0 col0
    #pragma unroll
    for (int p = 0; p < 2; p++) {
        int idx = tid + p * 256;
        int c4 = idx & 31, kk = idx >> 5;
        cpasync16(sa + (uint32_t)(kk * TLD + c4 * 4) * 4u,
                  src + (size_t)kk * row_stride + c4 * 4);
    }
}
// acc2[i][j]: rows i from Afrag (dup), col-pairs j from Bfrag (natural pairs)
__device__ __forceinline__ void mma_chunk(const float* As, const float* Bs,
                                          int ty, int tx, u64 acc2[8][4]) {
    #pragma unroll
    for (int kk = 0; kk < 16; kk++) {
        float4 a0 = *(const float4*)&As[kk * TLD + ty * 8];
        float4 a1 = *(const float4*)&As[kk * TLD + ty * 8 + 4];
        ulonglong2 b0 = *(const ulonglong2*)&Bs[kk * TLD + tx * 8];
        ulonglong2 b1 = *(const ulonglong2*)&Bs[kk * TLD + tx * 8 + 4];
        float am[8] = {a0.x, a0.y, a0.z, a0.w, a1.x, a1.y, a1.z, a1.w};
        #pragma unroll
        for (int i = 0; i < 8; i++) {
            u64 ad = pack2(am[i], am[i]);
            fma2(acc2[i][0], ad, b0.x); fma2(acc2[i][1], ad, b0.y);
            fma2(acc2[i][2], ad, b1.x); fma2(acc2[i][3], ad, b1.y);
        }
    }
}

// ---------------- kernel S: P^T[m][n] = exp(G.Fq^T), col sums -> g_D ----------
__global__ __launch_bounds__(256, 2) void s_kernel(
    const int* __restrict__ cmask, const int* __restrict__ smask)
{
    __shared__ float As[2][16 * TLD];   // G tile  (rows m)
    __shared__ float Bs[2][16 * TLD];   // Fq tile (cols n)
    __shared__ float red[16 * 132];
    __shared__ int cmS[128], smS[128];

    const int b = blockIdx.z, n0 = blockIdx.x * 128, m0 = blockIdx.y * 128;
    const int tid = threadIdx.x, ty = tid >> 4, tx = tid & 15;
    const float* Ab = g_G  + (size_t)b * CKEY * NPIX + m0;   // [ck][m]
    const float* Bb = g_Fq + (size_t)b * CKEY * NPIX + n0;   // [ck][n]
    uint32_t au[2] = {smem_u32(As[0]), smem_u32(As[1])};
    uint32_t bu[2] = {smem_u32(Bs[0]), smem_u32(Bs[1])};

    u64 acc2[8][4];
    #pragma unroll
    for (int i = 0; i < 8; i++)
        #pragma unroll
        for (int j = 0; j < 4; j++) acc2[i][j] = 0ULL;

    if (tid < 128) { cmS[tid] = cmask[b * NPIX + n0 + tid]; smS[tid] = smask[b * NPIX + m0 + tid]; }

    load_tile(au[0], Ab, NPIX, tid);
    load_tile(bu[0], Bb, NPIX, tid);
    CP_COMMIT(); CP_WAIT0(); __syncthreads();

    for (int c0 = 0; c0 < CKEY; c0 += 32) {
        if (c0 + 16 < CKEY) {
            load_tile(au[1], Ab + (size_t)(c0 + 16) * NPIX, NPIX, tid);
            load_tile(bu[1], Bb + (size_t)(c0 + 16) * NPIX, NPIX, tid);
        }
        CP_COMMIT();
        mma_chunk(As[0], Bs[0], ty, tx, acc2);
        CP_WAIT0(); __syncthreads();
        if (c0 + 32 < CKEY) {
            load_tile(au[0], Ab + (size_t)(c0 + 32) * NPIX, NPIX, tid);
            load_tile(bu[0], Bb + (size_t)(c0 + 32) * NPIX, NPIX, tid);
        }
        CP_COMMIT();
        if (c0 + 16 < CKEY) mma_chunk(As[1], Bs[1], ty, tx, acc2);
        CP_WAIT0(); __syncthreads();
    }

    // epilogue: exp + mask, write P^T, column(n) sums
    float* Pb = g_P + (size_t)b * NPIX * NPIX;
    float cs[8];
    #pragma unroll
    for (int j = 0; j < 8; j++) cs[j] = 0.f;
    #pragma unroll
    for (int i = 0; i < 8; i++) {
        int m = m0 + ty * 8 + i;
        bool sm0 = (smS[ty * 8 + i] == 0);
        float e[8];
        #pragma unroll
        for (int j = 0; j < 4; j++) {
            float lo, hi; unpack2(acc2[i][j], lo, hi);
            e[2*j]   = __expf(lo);
            e[2*j+1] = __expf(hi);
        }
        #pragma unroll
        for (int j = 0; j < 8; j++) {
            if (sm0 && cmS[tx * 8 + j]) e[j] = 0.f;
            cs[j] += e[j];
        }
        float* dst = Pb + (size_t)m * NPIX + n0 + tx * 8;
        *(float4*)dst       = make_float4(e[0], e[1], e[2], e[3]);
        *(float4*)(dst + 4) = make_float4(e[4], e[5], e[6], e[7]);
    }
    #pragma unroll
    for (int j = 0; j < 8; j += 4)
        *(float4*)&red[ty * 132 + tx * 8 + j] = make_float4(cs[j], cs[j+1], cs[j+2], cs[j+3]);
    __syncthreads();
    if (tid < 128) {
        float s = 0.f;
        #pragma unroll
        for (int t = 0; t < 16; t++) s += red[t * 132 + tid];
        atomicAdd(&g_D[(size_t)b * NPIX + n0 + tid], s);
    }
}

// ---------------- kernel PV: O = normalize(P @ HX) + fused epilogue ----------
__global__ __launch_bounds__(256, 2) void pv_kernel(
    const float* __restrict__ content, float* __restrict__ out)
{
    __shared__ float As[2][16 * TLD];   // P tile  (rows n)
    __shared__ float Bs[2][16 * TLD];   // HX tile (cols c')
    const int b = blockIdx.z, c0b = blockIdx.x * 128, n0 = blockIdx.y * 128;
    const int tid = threadIdx.x, ty = tid >> 4, tx = tid & 15;
    const float* Ab = g_P  + (size_t)b * NPIX * NPIX + n0;        // [m][n]
    const float* Bb = g_HX + (size_t)b * NPIX * (2 * CIN) + c0b;  // [m][c']
    uint32_t au[2] = {smem_u32(As[0]), smem_u32(As[1])};
    uint32_t bu[2] = {smem_u32(Bs[0]), smem_u32(Bs[1])};

    u64 acc2[8][4];
    #pragma unroll
    for (int i = 0; i < 8; i++)
        #pragma unroll
        for (int j = 0; j < 4; j++) acc2[i][j] = 0ULL;

    load_tile(au[0], Ab, NPIX, tid);
    load_tile(bu[0], Bb, 2 * CIN, tid);
    CP_COMMIT(); CP_WAIT0(); __syncthreads();

    for (int k0 = 0; k0 < NPIX; k0 += 32) {
        if (k0 + 16 < NPIX) {
            load_tile(au[1], Ab + (size_t)(k0 + 16) * NPIX, NPIX, tid);
            load_tile(bu[1], Bb + (size_t)(k0 + 16) * (2 * CIN), 2 * CIN, tid);
        }
        CP_COMMIT();
        mma_chunk(As[0], Bs[0], ty, tx, acc2);
        CP_WAIT0(); __syncthreads();
        if (k0 + 32 < NPIX) {
            load_tile(au[0], Ab + (size_t)(k0 + 32) * NPIX, NPIX, tid);
            load_tile(bu[0], Bb + (size_t)(k0 + 32) * (2 * CIN), 2 * CIN, tid);
        }
        CP_COMMIT();
        mma_chunk(As[1], Bs[1], ty, tx, acc2);
        CP_WAIT0(); __syncthreads();
    }

    const float* Cb = content + (size_t)b * CIN * NPIX;
    float* Ob = out + (size_t)b * CIN * NPIX;
    #pragma unroll
    for (int i = 0; i < 8; i++) {
        int n = n0 + ty * 8 + i;
        float invD = 1.f / g_D[(size_t)b * NPIX + n];
        #pragma unroll
        for (int j = 0; j < 4; j++) {
            float mv, qv; unpack2(acc2[i][j], mv, qv);
            float mean = mv * invD;
            float m2   = qv * invD;
            float sd = sqrtf(fmaxf(m2 - mean * mean, 0.f));
            int c = (c0b >> 1) + tx * 4 + j;      // c' pair -> channel
            float x = Cb[(size_t)c * NPIX + n];
            float nz = (x - g_sM[b * CIN + c]) * g_sR[b * CIN + c];
            Ob[(size_t)c * NPIX + n] = fmaf(sd, nz, mean);
        }
    }
}

extern "C" void kernel_launch(void* const* d_in, const int* in_sizes, int n_in,
                              void* d_out, int out_size) {
    const float* content = (const float*)d_in[0];
    const float* style   = (const float*)d_in[1];
    const float* ckey    = (const float*)d_in[2];
    const float* skey    = (const float*)d_in[3];
    const int*   cmask   = (const int*)d_in[4];
    const int*   smask   = (const int*)d_in[5];
    const float* Wf = (const float*)d_in[6];
    const float* bf = (const float*)d_in[7];
    const float* Wg = (const float*)d_in[8];
    const float* bg = (const float*)d_in[9];
    const float* Wh = (const float*)d_in[10];
    const float* bh = (const float*)d_in[11];
    float* out = (float*)d_out;

    float *Fq, *G, *HX, *D;
    cudaGetSymbolAddress((void**)&Fq, g_Fq);
    cudaGetSymbolAddress((void**)&G,  g_G);
    cudaGetSymbolAddress((void**)&HX, g_HX);
    cudaGetSymbolAddress((void**)&D,  g_D);

    proj_kernel<<<dim3(32, 7, BATCH), 256>>>(ckey,  Wf, bf, Fq, CKEY, CKEY, 0);
    proj_kernel<<<dim3(32, 7, BATCH), 256>>>(skey,  Wg, bg, G,  CKEY, CKEY, 0);
    proj_kernel<<<dim3(32, 4, BATCH), 256>>>(style, Wh, bh, HX, CIN, CIN, 1);
    mvn_stats_kernel<<<BATCH * CIN, 256>>>(content);
    zero_kernel<<<(BATCH * NPIX + 255) / 256, 256>>>(D, BATCH * NPIX);
    s_kernel<<<dim3(32, 32, BATCH), 256>>>(cmask, smask);
    pv_kernel<<<dim3(4, 32, BATCH), 256>>>(content, out);
}

// round 17
// speedup vs baseline: 2.9217x; 1.8078x over previous
#include <cuda_runtime.h>
#include <cuda_bf16.h>
#include <cstdint>
#include <math.h>

#define BATCH 4
#define CIN   256
#define CKEY  448
#define NPIX  4096
typedef __nv_bfloat16 bf16;

// ---------------- scratch ----------------
__device__ bf16 g_FqH[(size_t)BATCH * NPIX * CKEY];     // [b][n][ck]
__device__ bf16 g_FqL[(size_t)BATCH * NPIX * CKEY];
__device__ bf16 g_GH [(size_t)BATCH * NPIX * CKEY];     // [b][m][ck]
__device__ bf16 g_GL [(size_t)BATCH * NPIX * CKEY];
__device__ bf16 g_HXH[(size_t)BATCH * 2 * CIN * NPIX];  // [b][c'][m], c'=2c:v, 2c+1:v^2
__device__ bf16 g_HXL[(size_t)BATCH * 2 * CIN * NPIX];
__device__ bf16 g_PH [(size_t)BATCH * NPIX * NPIX];     // [b][n][m]
__device__ bf16 g_PL [(size_t)BATCH * NPIX * NPIX];
__device__ float g_D[BATCH * NPIX];
__device__ float g_sM[BATCH * CIN];
__device__ float g_sR[BATCH * CIN];

// ---------------- helpers ----------------
__device__ __forceinline__ uint32_t smem_u32(const void* p) {
    uint32_t a;
    asm("{ .reg .u64 t; cvta.to.shared.u64 t, %1; cvt.u32.u64 %0, t; }" : "=r"(a) : "l"(p));
    return a;
}
__device__ __forceinline__ void cpasync16(uint32_t dst, const void* src) {
    asm volatile("cp.async.cg.shared.global [%0], [%1], 16;" :: "r"(dst), "l"(src));
}
#define CP_COMMIT() asm volatile("cp.async.commit_group;")
#define CP_WAIT0()  asm volatile("cp.async.wait_group 0;")
#define CP_WAIT1()  asm volatile("cp.async.wait_group 1;")

#define LDSM4(r, addr) asm volatile( \
    "ldmatrix.sync.aligned.m8n8.x4.shared.b16 {%0,%1,%2,%3},[%4];" \
    : "=r"((r)[0]),"=r"((r)[1]),"=r"((r)[2]),"=r"((r)[3]) : "r"(addr))

#define MMA(d, a, b) asm volatile( \
    "mma.sync.aligned.m16n8k16.row.col.f32.bf16.bf16.f32 " \
    "{%0,%1,%2,%3},{%4,%5,%6,%7},{%8,%9},{%0,%1,%2,%3};" \
    : "+f"((d)[0]),"+f"((d)[1]),"+f"((d)[2]),"+f"((d)[3]) \
    : "r"((a)[0]),"r"((a)[1]),"r"((a)[2]),"r"((a)[3]),"r"((b)[0]),"r"((b)[1]))

__device__ __forceinline__ uint32_t bf16x2(float lo, float hi) {
    uint32_t r; asm("cvt.rn.satfinite.bf16x2.f32 %0, %1, %2;" : "=r"(r) : "f"(hi), "f"(lo));
    return r;
}
__device__ __forceinline__ float fexp(float s) {
    float y = s * 1.442695041f;
    y = fminf(fmaxf(y, -125.f), 125.f);
    float t = y + 12582912.f;
    float nf = t - 12582912.f;
    float f = y - nf;
    float p = 1.5403530e-4f;
    p = fmaf(p, f, 1.3333558e-3f);
    p = fmaf(p, f, 9.6181291e-3f);
    p = fmaf(p, f, 5.5504109e-2f);
    p = fmaf(p, f, 2.4022651e-1f);
    p = fmaf(p, f, 6.9314718e-1f);
    p = fmaf(p, f, 1.f);
    return __int_as_float(__float_as_int(p) + (((int)nf) << 23));
}

// ---------------- projection (fp32 math, split-bf16 out) ----------------
__global__ __launch_bounds__(256) void proj_kernel(
    const float* __restrict__ X, const float* __restrict__ W,
    const float* __restrict__ bias, bf16* __restrict__ oH, bf16* __restrict__ oL,
    int inC, int outC, int mode)
{
    __shared__ float Xs[128 * 20];
    __shared__ float Ws[64 * 20];
    const int n0 = blockIdx.x * 128, o0 = blockIdx.y * 64, b = blockIdx.z;
    const int tid = threadIdx.x, ty = tid >> 4, tx = tid & 15;
    const float* Xb = X + (size_t)b * inC * NPIX;

    float acc[8][4];
    #pragma unroll
    for (int i = 0; i < 8; i++)
        #pragma unroll
        for (int j = 0; j < 4; j++) acc[i][j] = 0.f;

    for (int c0 = 0; c0 < inC; c0 += 16) {
        __syncthreads();
        #pragma unroll
        for (int p = 0; p < 8; p++) {
            int idx = tid + p * 256, nn = idx & 127, cc = idx >> 7;
            Xs[nn * 20 + cc] = Xb[(size_t)(c0 + cc) * NPIX + n0 + nn];
        }
        #pragma unroll
        for (int p = 0; p < 4; p++) {
            int idx = tid + p * 256, cc = idx & 15, oo = idx >> 4;
            Ws[oo * 20 + cc] = W[(size_t)(o0 + oo) * inC + c0 + cc];
        }
        __syncthreads();
        #pragma unroll
        for (int cg = 0; cg < 4; cg++) {
            float4 bv[4];
            #pragma unroll
            for (int j = 0; j < 4; j++)
                bv[j] = *(const float4*)&Ws[(tx + 16 * j) * 20 + cg * 4];
            #pragma unroll
            for (int i = 0; i < 8; i++) {
                float4 av = *(const float4*)&Xs[(ty * 8 + i) * 20 + cg * 4];
                #pragma unroll
                for (int j = 0; j < 4; j++) {
                    acc[i][j] = fmaf(av.x, bv[j].x, acc[i][j]);
                    acc[i][j] = fmaf(av.y, bv[j].y, acc[i][j]);
                    acc[i][j] = fmaf(av.z, bv[j].z, acc[i][j]);
                    acc[i][j] = fmaf(av.w, bv[j].w, acc[i][j]);
                }
            }
        }
    }
    #pragma unroll
    for (int j = 0; j < 4; j++) {
        int o = o0 + tx + 16 * j;
        float bb = bias[o];
        #pragma unroll
        for (int i = 0; i < 8; i++) {
            int n = n0 + ty * 8 + i;
            float v = acc[i][j] + bb;
            if (mode == 0) {
                size_t idx = ((size_t)b * NPIX + n) * outC + o;
                bf16 h = __float2bfloat16(v);
                oH[idx] = h; oL[idx] = __float2bfloat16(v - __bfloat162float(h));
            } else {
                float v2 = v * v;
                size_t i1 = ((size_t)b * 2 * CIN + 2 * o) * NPIX + n;
                size_t i2 = i1 + NPIX;
                bf16 h1 = __float2bfloat16(v), h2 = __float2bfloat16(v2);
                oH[i1] = h1; oL[i1] = __float2bfloat16(v  - __bfloat162float(h1));
                oH[i2] = h2; oL[i2] = __float2bfloat16(v2 - __bfloat162float(h2));
            }
        }
    }
}

// ---------------- MVN stats ----------------
__global__ void mvn_stats_kernel(const float* __restrict__ x)
{
    const int bc = blockIdx.x;
    const float* p = x + (size_t)bc * NPIX;
    float s = 0.f, ss = 0.f;
    for (int i = threadIdx.x; i < NPIX; i += 256) {
        float v = p[i]; s += v; ss = fmaf(v, v, ss);
    }
    #pragma unroll
    for (int o = 16; o > 0; o >>= 1) {
        s  += __shfl_xor_sync(0xffffffffu, s,  o);
        ss += __shfl_xor_sync(0xffffffffu, ss, o);
    }
    __shared__ float shs[8], shss[8];
    int w = threadIdx.x >> 5, l = threadIdx.x & 31;
    if (l == 0) { shs[w] = s; shss[w] = ss; }
    __syncthreads();
    if (threadIdx.x == 0) {
        float S = 0.f, SS = 0.f;
        #pragma unroll
        for (int i = 0; i < 8; i++) { S += shs[i]; SS += shss[i]; }
        float mean = S / (float)NPIX;
        float var  = (SS - S * mean) / (float)(NPIX - 1);
        g_sM[bc] = mean; g_sR[bc] = rsqrtf(var + 1e-5f);
    }
}
__global__ void zero_kernel(float* p, int n) {
    int i = blockIdx.x * blockDim.x + threadIdx.x;
    if (i < n) p[i] = 0.f;
}

// ---------------- mma.sync GEMM core: 128x128 tile, K-chunk 64 ----------------
// smem: stage s at s*32768; A tile 128x64 bf16 (16KB) then B tile (16KB).
__device__ __forceinline__ void load_chunk(uint32_t sb, int stage,
    const bf16* A, const bf16* B, size_t stride, int tid)
{
    uint32_t base = sb + (uint32_t)stage * 32768u;
    #pragma unroll
    for (int p = 0; p < 4; p++) {
        int idx = tid + p * 256;
        int row = idx >> 3, c = idx & 7;
        uint32_t off = (uint32_t)(row * 128 + ((c ^ (row & 7)) << 4));
        cpasync16(base + off,          A + (size_t)row * stride + c * 8);
        cpasync16(base + 16384u + off, B + (size_t)row * stride + c * 8);
    }
}
__device__ __forceinline__ void mma_stage(uint32_t sb, int stage,
    int wr, int wc, int lane, float (&d)[4][4][4])
{
    uint32_t Ab = sb + (uint32_t)stage * 32768u, Bb = Ab + 16384u;
    #pragma unroll
    for (int ks = 0; ks < 4; ks++) {
        uint32_t a[4][4], bq[2][4];
        #pragma unroll
        for (int fm = 0; fm < 4; fm++) {
            int r = wr * 64 + fm * 16 + (lane & 7) + ((lane >> 3) & 1) * 8;
            int c = ks * 2 + (lane >> 4);
            LDSM4(a[fm], Ab + (uint32_t)(r * 128 + ((c ^ (r & 7)) << 4)));
        }
        #pragma unroll
        for (int p = 0; p < 2; p++) {
            int r = wc * 32 + p * 16 + (lane & 7) + ((lane >> 4) & 1) * 8;
            int c = ks * 2 + ((lane >> 3) & 1);
            LDSM4(bq[p], Bb + (uint32_t)(r * 128 + ((c ^ (r & 7)) << 4)));
        }
        #pragma unroll
        for (int fm = 0; fm < 4; fm++)
            #pragma unroll
            for (int fn = 0; fn < 4; fn++)
                MMA(d[fm][fn], a[fm], (&bq[fn >> 1][(fn & 1) * 2]));
    }
}
__device__ __forceinline__ void gemm_main(uint32_t sb,
    const bf16* const* Ap, const bf16* const* Bp,
    int cps, size_t stride, int tid, int wr, int wc, int lane,
    float (&d)[4][4][4])
{
    const int total = 3 * cps;
    load_chunk(sb, 0, Ap[0], Bp[0], stride, tid);
    CP_COMMIT();
    for (int ch = 0; ch < total; ch++) {
        if (ch + 1 < total) {
            int seg = (ch + 1) / cps, off = (ch + 1) - seg * cps;
            load_chunk(sb, (ch + 1) & 1, Ap[seg] + (size_t)off * 64,
                       Bp[seg] + (size_t)off * 64, stride, tid);
            CP_COMMIT(); CP_WAIT1();
        } else CP_WAIT0();
        __syncthreads();
        mma_stage(sb, ch & 1, wr, wc, lane, d);
        __syncthreads();
    }
}

// ---------------- S kernel: P[n][m] = exp(Fq.G^T) masked; denominators -------
__global__ __launch_bounds__(256) void s_kernel(
    const int* __restrict__ cmask, const int* __restrict__ smask)
{
    extern __shared__ char dyn[];
    __shared__ int cmS[128], smS[128];
    uint32_t sb = smem_u32(dyn);
    const int b = blockIdx.z, m0 = blockIdx.x * 128, n0 = blockIdx.y * 128;
    const int tid = threadIdx.x, wid = tid >> 5, lane = tid & 31;
    const int wr = wid >> 2, wc = wid & 3, lq = lane >> 2, le = lane & 3;

    if (tid < 128) { cmS[tid] = cmask[b * NPIX + n0 + tid]; smS[tid] = smask[b * NPIX + m0 + tid]; }

    float d[4][4][4];
    #pragma unroll
    for (int i = 0; i < 4; i++)
        #pragma unroll
        for (int j = 0; j < 4; j++)
            #pragma unroll
            for (int k = 0; k < 4; k++) d[i][j][k] = 0.f;

    const bf16* FqH = g_FqH + ((size_t)b * NPIX + n0) * CKEY;
    const bf16* FqL = g_FqL + ((size_t)b * NPIX + n0) * CKEY;
    const bf16* GH  = g_GH  + ((size_t)b * NPIX + m0) * CKEY;
    const bf16* GL  = g_GL  + ((size_t)b * NPIX + m0) * CKEY;
    const bf16* Ap[3] = {FqH, FqH, FqL};
    const bf16* Bp[3] = {GH,  GL,  GH};
    gemm_main(sb, Ap, Bp, CKEY / 64, CKEY, tid, wr, wc, lane, d);

    #pragma unroll
    for (int fm = 0; fm < 4; fm++) {
        #pragma unroll
        for (int half = 0; half < 2; half++) {
            int rloc = wr * 64 + fm * 16 + lq + 8 * half;
            int n = n0 + rloc;
            int cm = cmS[rloc];
            float rsum = 0.f;
            uint32_t hw[4], lw[4];
            #pragma unroll
            for (int fn = 0; fn < 4; fn++) {
                int cl = wc * 32 + fn * 8 + 2 * le;
                float e0 = fexp(d[fm][fn][half * 2 + 0]);
                float e1 = fexp(d[fm][fn][half * 2 + 1]);
                if (cm) {
                    if (smS[cl] == 0)     e0 = 0.f;
                    if (smS[cl + 1] == 0) e1 = 0.f;
                }
                rsum += e0 + e1;
                uint32_t h = bf16x2(e0, e1);
                hw[fn] = h;
                float h0 = __uint_as_float(h << 16);
                float h1 = __uint_as_float(h & 0xFFFF0000u);
                lw[fn] = bf16x2(e0 - h0, e1 - h1);
            }
            rsum += __shfl_xor_sync(0xffffffffu, rsum, 1);
            rsum += __shfl_xor_sync(0xffffffffu, rsum, 2);
            if (le == 0) atomicAdd(&g_D[b * NPIX + n], rsum);
            bf16* PHr = g_PH + ((size_t)b * NPIX + n) * NPIX + m0 + wc * 32 + 2 * le;
            bf16* PLr = g_PL + ((size_t)b * NPIX + n) * NPIX + m0 + wc * 32 + 2 * le;
            #pragma unroll
            for (int fn = 0; fn < 4; fn++) {
                *(uint32_t*)(PHr + fn * 8) = hw[fn];
                *(uint32_t*)(PLr + fn * 8) = lw[fn];
            }
        }
    }
}

// ---------------- PV kernel: O[n][c'] = P.HX^T; fused epilogue ----------------
__global__ __launch_bounds__(256) void pv_kernel(
    const float* __restrict__ content, float* __restrict__ out)
{
    extern __shared__ char dyn[];
    uint32_t sb = smem_u32(dyn);
    const int b = blockIdx.z, c0b = blockIdx.x * 128, n0 = blockIdx.y * 128;
    const int tid = threadIdx.x, wid = tid >> 5, lane = tid & 31;
    const int wr = wid >> 2, wc = wid & 3, lq = lane >> 2, le = lane & 3;

    float d[4][4][4];
    #pragma unroll
    for (int i = 0; i < 4; i++)
        #pragma unroll
        for (int j = 0; j < 4; j++)
            #pragma unroll
            for (int k = 0; k < 4; k++) d[i][j][k] = 0.f;

    const bf16* PH  = g_PH  + ((size_t)b * NPIX + n0) * NPIX;
    const bf16* PL  = g_PL  + ((size_t)b * NPIX + n0) * NPIX;
    const bf16* HXH = g_HXH + ((size_t)b * 2 * CIN + c0b) * NPIX;
    const bf16* HXL = g_HXL + ((size_t)b * 2 * CIN + c0b) * NPIX;
    const bf16* Ap[3] = {PH,  PH,  PL};
    const bf16* Bp[3] = {HXH, HXL, HXH};
    gemm_main(sb, Ap, Bp, NPIX / 64, NPIX, tid, wr, wc, lane, d);

    #pragma unroll
    for (int fm = 0; fm < 4; fm++) {
        #pragma unroll
        for (int half = 0; half < 2; half++) {
            int n = n0 + wr * 64 + fm * 16 + lq + 8 * half;
            float invD = 1.f / g_D[b * NPIX + n];
            #pragma unroll
            for (int fn = 0; fn < 4; fn++) {
                int c = (c0b >> 1) + wc * 16 + fn * 4 + le;
                float mean = d[fm][fn][half * 2 + 0] * invD;
                float m2   = d[fm][fn][half * 2 + 1] * invD;
                float sd = sqrtf(fmaxf(m2 - mean * mean, 0.f));
                float x = content[((size_t)b * CIN + c) * NPIX + n];
                float nz = (x - g_sM[b * CIN + c]) * g_sR[b * CIN + c];
                out[((size_t)b * CIN + c) * NPIX + n] = fmaf(sd, nz, mean);
            }
        }
    }
}

extern "C" void kernel_launch(void* const* d_in, const int* in_sizes, int n_in,
                              void* d_out, int out_size) {
    const float* content = (const float*)d_in[0];
    const float* style   = (const float*)d_in[1];
    const float* ckey    = (const float*)d_in[2];
    const float* skey    = (const float*)d_in[3];
    const int*   cmask   = (const int*)d_in[4];
    const int*   smask   = (const int*)d_in[5];
    const float* Wf = (const float*)d_in[6];
    const float* bfb = (const float*)d_in[7];
    const float* Wg = (const float*)d_in[8];
    const float* bg = (const float*)d_in[9];
    const float* Wh = (const float*)d_in[10];
    const float* bh = (const float*)d_in[11];
    float* out = (float*)d_out;

    bf16 *FqH, *FqL, *GH, *GL, *HXH, *HXL; float* D;
    cudaGetSymbolAddress((void**)&FqH, g_FqH);
    cudaGetSymbolAddress((void**)&FqL, g_FqL);
    cudaGetSymbolAddress((void**)&GH,  g_GH);
    cudaGetSymbolAddress((void**)&GL,  g_GL);
    cudaGetSymbolAddress((void**)&HXH, g_HXH);
    cudaGetSymbolAddress((void**)&HXL, g_HXL);
    cudaGetSymbolAddress((void**)&D,   g_D);

    const int SMEM = 65536;
    cudaFuncSetAttribute(s_kernel,  cudaFuncAttributeMaxDynamicSharedMemorySize, SMEM);
    cudaFuncSetAttribute(pv_kernel, cudaFuncAttributeMaxDynamicSharedMemorySize, SMEM);

    proj_kernel<<<dim3(32, 7, BATCH), 256>>>(ckey,  Wf, bfb, FqH, FqL, CKEY, CKEY, 0);
    proj_kernel<<<dim3(32, 7, BATCH), 256>>>(skey,  Wg, bg,  GH,  GL,  CKEY, CKEY, 0);
    proj_kernel<<<dim3(32, 4, BATCH), 256>>>(style, Wh, bh,  HXH, HXL, CIN,  CIN,  1);
    mvn_stats_kernel<<<BATCH * CIN, 256>>>(content);
    zero_kernel<<<(BATCH * NPIX + 255) / 256, 256>>>(D, BATCH * NPIX);
    s_kernel<<<dim3(32, 32, BATCH), 256, SMEM>>>(cmask, smask);
    pv_kernel<<<dim3(4, 32, BATCH), 256, SMEM>>>(content, out);
}